// round 7
// baseline (speedup 1.0000x reference)
#include <cuda_runtime.h>
#include <cuda_bf16.h>

// Fixed problem shape (from reference setup_inputs): B=32, H=W=768.
// LEVELS=(1,2,3) -> finest grid 8x8 regions of 96x96.
#define IMG_H   768
#define IMG_W   768
#define IMG_N   (IMG_H * IMG_W)          // 589824
#define REG     96
#define NREG    64                       // 8x8 regions per image
#define MAXB    32
#define NSUB    8                        // 12-row slabs per 96-row band
#define NENT    (MAXB * NREG * NSUB)     // 16384 scratch entries

__device__ float g_sq2[NENT];            // per-(region,sub) sum of (p-g)^2
__device__ float g_rd2[NENT];            // per-(region,sub) sum of (p-g)
__device__ unsigned int g_counter = 0;   // last-block-done counter

// ---------------------------------------------------------------------------
// Fused kernel, LINEAR-SLAB decomposition:
// block = (batch, band ry, sub) -> one contiguous 12-row x 768-col slab
// (36 KB per tensor, purely sequential float4 traffic for DRAM row locality).
// Region rx recovered arithmetically; per-block deterministic ownership
// reduce (warp w owns rx=w) emits 8 (d,s) sub-partials.
// LAST arriving block runs the smem-staged finish pyramid.
// ---------------------------------------------------------------------------
__global__ __launch_bounds__(256, 8)
void saf_fused_kernel(const float* __restrict__ pred,
                      const float* __restrict__ gt,
                      const float* __restrict__ rgb,
                      const float* __restrict__ thermal,
                      float* __restrict__ out,
                      int B)
{
    const int blk = blockIdx.x;
    const int b   = blk >> 6;            // batch
    const int ry  = (blk >> 3) & 7;      // band 0..7
    const int sub = blk & 7;             // 12-row slab within band

    // slab: 12 contiguous rows = 9216 floats = 2304 float4
    const size_t base = (size_t)b * IMG_N + ((size_t)ry * REG + (size_t)sub * 12) * IMG_W;
    const float4* __restrict__ p4 = reinterpret_cast<const float4*>(pred + base);
    const float4* __restrict__ g4 = reinterpret_cast<const float4*>(gt   + base);

    const int t = threadIdx.x;

    // 9 iterations; k%3 selects one of 3 region bins per thread
    float accd[3] = {0.f, 0.f, 0.f};
    float accs[3] = {0.f, 0.f, 0.f};

#pragma unroll
    for (int k = 0; k < 9; ++k) {
        const int off = t + k * 256;     // fully linear
        float4 a  = __ldcs(&p4[off]);
        float4 bb = __ldcs(&g4[off]);
        const int m = k % 3;
        float d0 = a.x - bb.x;
        float d1 = a.y - bb.y;
        float d2 = a.z - bb.z;
        float d3 = a.w - bb.w;
        accd[m] += (d0 + d1) + (d2 + d3);
        accs[m] += d0 * d0 + d1 * d1 + d2 * d2 + d3 * d3;
    }

    // stage per-thread partials: layout [m][t]
    __shared__ float sm_pd[3 * 256];
    __shared__ float sm_ps[3 * 256];
#pragma unroll
    for (int m = 0; m < 3; ++m) {
        sm_pd[m * 256 + t] = accd[m];
        sm_ps[m * 256 + t] = accs[m];
    }
    __syncthreads();

    // ownership reduce: warp w gathers all entries whose rx == w.
    // entry i = m*256 + tt  ->  col4 = (tt + 64*m) % 192, rx = col4/24.
    const int wid = t >> 5;
    const int lid = t & 31;
    {
        float dsum = 0.f, ssum = 0.f;
        for (int i = lid; i < 768; i += 32) {
            const int tt = i & 255;
            const int mm = i >> 8;
            const int col4 = (tt + 64 * mm) % 192;
            if ((col4 / 24) == wid) {
                dsum += sm_pd[i];
                ssum += sm_ps[i];
            }
        }
#pragma unroll
        for (int o = 16; o > 0; o >>= 1) {
            dsum += __shfl_xor_sync(0xFFFFFFFFu, dsum, o);
            ssum += __shfl_xor_sync(0xFFFFFFFFu, ssum, o);
        }
        if (lid == 0) {
            // entry index: (((b*8 + ry)*8 + rx) * 8 + sub)
            const int e = (((b * 8 + ry) * 8 + wid) << 3) + sub;
            g_rd2[e] = dsum;
            g_sq2[e] = ssum;
        }
    }

    // ----- last-block-done handshake -----
    __shared__ unsigned int s_last;
    __threadfence();
    if (t == 0) {
        unsigned int old = atomicAdd(&g_counter, 1u);
        s_last = (old == (unsigned int)(gridDim.x - 1));
    }
    __syncthreads();
    if (!s_last) return;
    __threadfence();
    if (t == 0) g_counter = 0;           // reset for next graph replay

    // ===== finish phase: smem-staged parallel pyramid =====
    const int nent = B * NREG * NSUB;    // 16384
    const int nreg = B * NREG;           // 2048

    __shared__ float sm_r[MAXB * 64];    // 8 KB
    __shared__ float sm_d4[MAXB * 16];   // 2 KB
    __shared__ float sm_d2[MAXB * 4];    // 0.5 KB

    float sq = 0.0f;
    for (int i = t; i < nent; i += 256) sq += __ldcg(&g_sq2[i]);

    // collapse sub axis into per-region diffs
    for (int j = t; j < nreg; j += 256) {
        float v = 0.f;
#pragma unroll
        for (int s2 = 0; s2 < NSUB; ++s2) v += __ldcg(&g_rd2[j * NSUB + s2]);
        sm_r[j] = v;
    }
    __syncthreads();

    // level 3
    float l3 = 0.0f;
    for (int i = t; i < nreg; i += 256) l3 += fabsf(sm_r[i]);

    // level 2: B*16 cells
    float l2 = 0.0f;
    for (int j = t; j < B * 16; j += 256) {
        const int bb2 = j >> 4;
        const int q   = j & 15;
        const int qi  = q >> 2;
        const int qj  = q & 3;
        const float* rr = &sm_r[bb2 * 64];
        float s = rr[(2 * qi) * 8 + 2 * qj] + rr[(2 * qi) * 8 + 2 * qj + 1]
                + rr[(2 * qi + 1) * 8 + 2 * qj] + rr[(2 * qi + 1) * 8 + 2 * qj + 1];
        sm_d4[j] = s;
        l2 += fabsf(s);
    }
    __syncthreads();

    // level 1: B*4 cells
    float l1 = 0.0f;
    for (int j = t; j < B * 4; j += 256) {
        const int bb2 = j >> 2;
        const int q   = j & 3;
        const int qi  = q >> 1;
        const int qj  = q & 1;
        const float* dd = &sm_d4[bb2 * 16];
        float s = dd[(2 * qi) * 4 + 2 * qj] + dd[(2 * qi) * 4 + 2 * qj + 1]
                + dd[(2 * qi + 1) * 4 + 2 * qj] + dd[(2 * qi + 1) * 4 + 2 * qj + 1];
        sm_d2[j] = s;
        l1 += fabsf(s);
    }
    __syncthreads();

    // count loss
    float cnt = 0.0f;
    for (int j = t; j < B; j += 256) {
        float s = sm_d2[j * 4] + sm_d2[j * 4 + 1] + sm_d2[j * 4 + 2] + sm_d2[j * 4 + 3];
        cnt += fabsf(s);
    }

    // domain CE: rgb label 0, thermal label 1
    float dom = 0.0f;
    for (int j = t; j < B; j += 256) {
        float x0 = rgb[2 * j], x1 = rgb[2 * j + 1];
        float m  = fmaxf(x0, x1);
        float lse = m + logf(expf(x0 - m) + expf(x1 - m));
        dom += lse - x0;
        float y0 = thermal[2 * j], y1 = thermal[2 * j + 1];
        m   = fmaxf(y0, y1);
        lse = m + logf(expf(y0 - m) + expf(y1 - m));
        dom += lse - y1;
    }

    float reg = l1 + l2 + l3;

    __shared__ float s_sq[256], s_cnt[256], s_reg[256], s_dom[256];
    s_sq[t] = sq; s_cnt[t] = cnt; s_reg[t] = reg; s_dom[t] = dom;
    __syncthreads();
#pragma unroll
    for (int o = 128; o > 0; o >>= 1) {
        if (t < o) {
            s_sq[t]  += s_sq[t + o];
            s_cnt[t] += s_cnt[t + o];
            s_reg[t] += s_reg[t + o];
            s_dom[t] += s_dom[t + o];
        }
        __syncthreads();
    }

    if (t == 0) {
        float invB = 1.0f / (float)B;
        float density  = s_sq[0] / ((float)B * (float)IMG_N);
        float count_l  = s_cnt[0] * invB;
        float regional = s_reg[0] * invB / (3.0f * 64.0f);  // len(LEVELS)*last_cells^2
        float domain   = (s_dom[0] * invB) * 0.5f;          // (ce_rgb + ce_th)/2
        // W_DENSITY=100, W_COUNT=0.001, W_REGIONAL=1.0, W_DOMAIN=0.5
        out[0] = 100.0f * density + 0.001f * count_l + 1.0f * regional + 0.5f * domain;
    }
}

extern "C" void kernel_launch(void* const* d_in, const int* in_sizes, int n_in,
                              void* d_out, int out_size)
{
    const float* pred    = (const float*)d_in[0];
    const float* gt      = (const float*)d_in[1];
    const float* rgb     = (const float*)d_in[2];
    const float* thermal = (const float*)d_in[3];
    float* out = (float*)d_out;

    const int B = in_sizes[0] / IMG_N;   // 32 for this problem

    saf_fused_kernel<<<B * NREG, 256>>>(pred, gt, rgb, thermal, out, B);
}

// round 8
// speedup vs baseline: 1.3815x; 1.3815x over previous
#include <cuda_runtime.h>
#include <cuda_bf16.h>
#include <cstdint>

// Fixed problem shape: B=32, H=W=768. LEVELS=(1,2,3) -> 8x8 regions of 96x96.
#define IMG_H   768
#define IMG_W   768
#define IMG_N   (IMG_H * IMG_W)          // 589824
#define NREG    64                       // 8x8 regions per image
#define MAXB    32

#define RPC      6                       // rows per chunk
#define CHUNK_F  (RPC * IMG_W)           // 4608 floats
#define CHUNK_BY (CHUNK_F * 4)           // 18432 bytes
#define NCHUNK   16                      // 96 rows / 6
#define DYN_SMEM (2 * 2 * CHUNK_BY)      // 2 stages x 2 tensors = 73728 B

__device__ float g_sqsum[MAXB * NREG];
__device__ float g_rdiff[MAXB * NREG];
__device__ unsigned int g_counter = 0;

__device__ __forceinline__ unsigned smem_u32(const void* p) {
    unsigned a;
    asm("{ .reg .u64 t; cvta.to.shared.u64 t, %1; cvt.u32.u64 %0, t; }"
        : "=r"(a) : "l"(p));
    return a;
}

__device__ __forceinline__ void mbar_init(unsigned mb, unsigned cnt) {
    asm volatile("mbarrier.init.shared.b64 [%0], %1;" :: "r"(mb), "r"(cnt) : "memory");
}

__device__ __forceinline__ void mbar_expect_tx(unsigned mb, unsigned bytes) {
    asm volatile("mbarrier.arrive.expect_tx.shared.b64 _, [%0], %1;"
                 :: "r"(mb), "r"(bytes) : "memory");
}

__device__ __forceinline__ void mbar_wait(unsigned mb, unsigned phase) {
    asm volatile(
        "{\n\t"
        ".reg .pred P;\n\t"
        "WAIT_%=:\n\t"
        "mbarrier.try_wait.parity.acquire.cta.shared::cta.b64 P, [%0], %1, 0x989680;\n\t"
        "@P bra WDONE_%=;\n\t"
        "bra WAIT_%=;\n\t"
        "WDONE_%=:\n\t"
        "}" :: "r"(mb), "r"(phase) : "memory");
}

__device__ __forceinline__ void tma_bulk_1d(unsigned dst_smem, const void* src,
                                            unsigned bytes, unsigned mb) {
    asm volatile(
        "cp.async.bulk.shared::cluster.global.mbarrier::complete_tx::bytes "
        "[%0], [%1], %2, [%3];"
        :: "r"(dst_smem), "l"(src), "r"(bytes), "r"(mb) : "memory");
}

// ---------------------------------------------------------------------------
// TMA-streamed fused kernel.
// Block = (batch, band ry). Double-buffered cp.async.bulk brings 6-row
// chunks of pred+gt into smem; warp w reduces region column rx=w.
// Last arriving block runs the smem-staged finish pyramid.
// ---------------------------------------------------------------------------
extern __shared__ float dynbuf[];        // [stage][tensor][CHUNK_F]

__global__ __launch_bounds__(256, 2)
void saf_tma_kernel(const float* __restrict__ pred,
                    const float* __restrict__ gt,
                    const float* __restrict__ rgb,
                    const float* __restrict__ thermal,
                    float* __restrict__ out,
                    int B)
{
    const int blk = blockIdx.x;
    const int b   = blk >> 3;            // batch
    const int ry  = blk & 7;             // band 0..7

    const size_t base = (size_t)b * IMG_N + (size_t)ry * 96 * IMG_W;
    const float* psrc = pred + base;
    const float* gsrc = gt   + base;

    const int t    = threadIdx.x;
    const int w    = t >> 5;             // warp = region column rx
    const int lane = t & 31;

    __shared__ __align__(8) unsigned long long mbar_store[2];
    const unsigned mb0 = smem_u32(&mbar_store[0]);
    const unsigned mb1 = mb0 + 8;

    if (t == 0) { mbar_init(mb0, 1); mbar_init(mb1, 1); }
    __syncthreads();

    const unsigned sbuf0 = smem_u32(dynbuf);

    // prologue: fill both stages
    if (t == 0) {
#pragma unroll
        for (int k = 0; k < 2; ++k) {
            const unsigned mb = k ? mb1 : mb0;
            mbar_expect_tx(mb, 2 * CHUNK_BY);
            tma_bulk_1d(sbuf0 + (k * 2 + 0) * CHUNK_BY, psrc + (size_t)k * CHUNK_F, CHUNK_BY, mb);
            tma_bulk_1d(sbuf0 + (k * 2 + 1) * CHUNK_BY, gsrc + (size_t)k * CHUNK_F, CHUNK_BY, mb);
        }
    }

    float dsum = 0.0f, ssum = 0.0f;
    unsigned phase0 = 0, phase1 = 0;

    for (int k = 0; k < NCHUNK; ++k) {
        const int s = k & 1;
        if (s == 0) { mbar_wait(mb0, phase0); phase0 ^= 1; }
        else        { mbar_wait(mb1, phase1); phase1 ^= 1; }

        const float4* p4 = reinterpret_cast<const float4*>(dynbuf + (s * 2 + 0) * CHUNK_F);
        const float4* g4 = reinterpret_cast<const float4*>(dynbuf + (s * 2 + 1) * CHUNK_F);

        // warp w consumes float4 columns [24w, 24w+24) over 6 rows: 144 float4
#pragma unroll
        for (int i = 0; i < 5; ++i) {
            const int j = lane + i * 32;
            if (j < 144) {
                const int row = j / 24;
                const int c   = j - row * 24;
                const int idx = row * 192 + w * 24 + c;
                float4 a  = p4[idx];
                float4 bb = g4[idx];
                float d0 = a.x - bb.x;
                float d1 = a.y - bb.y;
                float d2 = a.z - bb.z;
                float d3 = a.w - bb.w;
                dsum += (d0 + d1) + (d2 + d3);
                ssum += d0 * d0 + d1 * d1 + d2 * d2 + d3 * d3;
            }
        }

        __syncthreads();                 // stage s fully consumed
        if (t == 0 && k + 2 < NCHUNK) {
            const unsigned mb = s ? mb1 : mb0;
            mbar_expect_tx(mb, 2 * CHUNK_BY);
            tma_bulk_1d(sbuf0 + (s * 2 + 0) * CHUNK_BY, psrc + (size_t)(k + 2) * CHUNK_F, CHUNK_BY, mb);
            tma_bulk_1d(sbuf0 + (s * 2 + 1) * CHUNK_BY, gsrc + (size_t)(k + 2) * CHUNK_F, CHUNK_BY, mb);
        }
    }

    // warp reduce -> one region per warp
#pragma unroll
    for (int o = 16; o > 0; o >>= 1) {
        dsum += __shfl_xor_sync(0xFFFFFFFFu, dsum, o);
        ssum += __shfl_xor_sync(0xFFFFFFFFu, ssum, o);
    }
    if (lane == 0) {
        const int r = ry * 8 + w;
        g_rdiff[b * NREG + r] = dsum;
        g_sqsum[b * NREG + r] = ssum;
    }

    // ----- last-block-done handshake -----
    __shared__ unsigned int s_last;
    __threadfence();
    if (t == 0) {
        unsigned int old = atomicAdd(&g_counter, 1u);
        s_last = (old == (unsigned int)(gridDim.x - 1));
    }
    __syncthreads();
    if (!s_last) return;
    __threadfence();
    if (t == 0) g_counter = 0;           // reset for next graph replay

    // ===== finish phase: smem-staged parallel pyramid =====
    const int nreg = B * NREG;           // 2048

    __shared__ float sm_r[MAXB * 64];    // 8 KB
    __shared__ float sm_d4[MAXB * 16];   // 2 KB
    __shared__ float sm_d2[MAXB * 4];    // 0.5 KB

    float sq = 0.0f;
    for (int i = t; i < nreg; i += 256) {
        sq += __ldcg(&g_sqsum[i]);
        sm_r[i] = __ldcg(&g_rdiff[i]);
    }
    __syncthreads();

    float l3 = 0.0f;
    for (int i = t; i < nreg; i += 256) l3 += fabsf(sm_r[i]);

    float l2 = 0.0f;
    for (int j = t; j < B * 16; j += 256) {
        const int bb2 = j >> 4;
        const int q   = j & 15;
        const int qi  = q >> 2;
        const int qj  = q & 3;
        const float* rr = &sm_r[bb2 * 64];
        float s = rr[(2 * qi) * 8 + 2 * qj] + rr[(2 * qi) * 8 + 2 * qj + 1]
                + rr[(2 * qi + 1) * 8 + 2 * qj] + rr[(2 * qi + 1) * 8 + 2 * qj + 1];
        sm_d4[j] = s;
        l2 += fabsf(s);
    }
    __syncthreads();

    float l1 = 0.0f;
    for (int j = t; j < B * 4; j += 256) {
        const int bb2 = j >> 2;
        const int q   = j & 3;
        const int qi  = q >> 1;
        const int qj  = q & 1;
        const float* dd = &sm_d4[bb2 * 16];
        float s = dd[(2 * qi) * 4 + 2 * qj] + dd[(2 * qi) * 4 + 2 * qj + 1]
                + dd[(2 * qi + 1) * 4 + 2 * qj] + dd[(2 * qi + 1) * 4 + 2 * qj + 1];
        sm_d2[j] = s;
        l1 += fabsf(s);
    }
    __syncthreads();

    float cnt = 0.0f;
    for (int j = t; j < B; j += 256) {
        float s = sm_d2[j * 4] + sm_d2[j * 4 + 1] + sm_d2[j * 4 + 2] + sm_d2[j * 4 + 3];
        cnt += fabsf(s);
    }

    float dom = 0.0f;
    for (int j = t; j < B; j += 256) {
        float x0 = rgb[2 * j], x1 = rgb[2 * j + 1];
        float m  = fmaxf(x0, x1);
        float lse = m + logf(expf(x0 - m) + expf(x1 - m));
        dom += lse - x0;
        float y0 = thermal[2 * j], y1 = thermal[2 * j + 1];
        m   = fmaxf(y0, y1);
        lse = m + logf(expf(y0 - m) + expf(y1 - m));
        dom += lse - y1;
    }

    float reg = l1 + l2 + l3;

    __shared__ float s_sq[256], s_cnt[256], s_reg[256], s_dom[256];
    s_sq[t] = sq; s_cnt[t] = cnt; s_reg[t] = reg; s_dom[t] = dom;
    __syncthreads();
#pragma unroll
    for (int o = 128; o > 0; o >>= 1) {
        if (t < o) {
            s_sq[t]  += s_sq[t + o];
            s_cnt[t] += s_cnt[t + o];
            s_reg[t] += s_reg[t + o];
            s_dom[t] += s_dom[t + o];
        }
        __syncthreads();
    }

    if (t == 0) {
        float invB = 1.0f / (float)B;
        float density  = s_sq[0] / ((float)B * (float)IMG_N);
        float count_l  = s_cnt[0] * invB;
        float regional = s_reg[0] * invB / (3.0f * 64.0f);
        float domain   = (s_dom[0] * invB) * 0.5f;
        // W_DENSITY=100, W_COUNT=0.001, W_REGIONAL=1.0, W_DOMAIN=0.5
        out[0] = 100.0f * density + 0.001f * count_l + 1.0f * regional + 0.5f * domain;
    }
}

extern "C" void kernel_launch(void* const* d_in, const int* in_sizes, int n_in,
                              void* d_out, int out_size)
{
    const float* pred    = (const float*)d_in[0];
    const float* gt      = (const float*)d_in[1];
    const float* rgb     = (const float*)d_in[2];
    const float* thermal = (const float*)d_in[3];
    float* out = (float*)d_out;

    const int B = in_sizes[0] / IMG_N;   // 32 for this problem

    cudaFuncSetAttribute(saf_tma_kernel,
                         cudaFuncAttributeMaxDynamicSharedMemorySize, DYN_SMEM);
    saf_tma_kernel<<<B * 8, 256, DYN_SMEM>>>(pred, gt, rgb, thermal, out, B);
}